// round 12
// baseline (speedup 1.0000x reference)
#include <cuda_runtime.h>
#include <cuda_fp16.h>
#include <cstdint>

#define DIM 128
#define MAXN 50176
#define SLOTS 128
#define SLOPE 0.2f
#define PAD 136          // halfs per smem row (272B) — conflict-free ldmatrix
typedef unsigned long long u64;

// ---------------- scratch ----------------
__device__ __align__(16) float  g_att[2 * DIM + 8];
__device__ __align__(16) float  g_s1[MAXN];
__device__ __align__(16) float  g_s2[MAXN];
__device__ __align__(16) __half g_featH[(size_t)MAXN * DIM];
__device__ __align__(16) __half g_aggH[(size_t)MAXN * DIM];     // fp16 aggregate
__device__ __align__(16) int    g_counts[MAXN];                 // self-zeroing
__device__ __align__(16) unsigned g_bucket[(size_t)MAXN * SLOTS]; // (halfW<<16)|src
__device__ __align__(16) __half g_W1T[DIM * PAD];  // W1^T padded: [n][k] = W1[k][n]
__device__ __align__(16) __half g_W2T[DIM * PAD];

__device__ __forceinline__ float lrelu(float x) { return x > 0.f ? x : SLOPE * x; }

__device__ __forceinline__ void mma16816(float* c, const uint32_t* a,
                                         uint32_t b0, uint32_t b1) {
    asm volatile(
        "mma.sync.aligned.m16n8k16.row.col.f32.f16.f16.f32 "
        "{%0,%1,%2,%3}, {%4,%5,%6,%7}, {%8,%9}, {%0,%1,%2,%3};"
        : "+f"(c[0]), "+f"(c[1]), "+f"(c[2]), "+f"(c[3])
        : "r"(a[0]), "r"(a[1]), "r"(a[2]), "r"(a[3]), "r"(b0), "r"(b1));
}
__device__ __forceinline__ void ldmatrix4(uint32_t* a, uint32_t addr) {
    asm volatile("ldmatrix.sync.aligned.m8n8.x4.shared.b16 {%0,%1,%2,%3}, [%4];"
                 : "=r"(a[0]), "=r"(a[1]), "=r"(a[2]), "=r"(a[3]) : "r"(addr));
}

// ---------------- K0: att projection vectors + W^T fp16 tables ----------------
__global__ void k_attw(const float* __restrict__ Watt_w, const float* __restrict__ Watt_b,
                       const float* __restrict__ a,
                       const float* __restrict__ W1_w, const float* __restrict__ W2_w) {
    int tid = threadIdx.x;
    if (blockIdx.x == 0) {
        __shared__ float sc1[DIM], sc2[DIM];
        if (tid < DIM) {
            float v1 = 0.f, v2 = 0.f;
            #pragma unroll 8
            for (int j = 0; j < DIM; j++) {
                float w = Watt_w[tid * DIM + j];
                v1 += w * a[j];
                v2 += w * a[DIM + j];
            }
            g_att[tid] = v1;
            g_att[DIM + tid] = v2;
            sc1[tid] = Watt_b[tid] * a[tid];
            sc2[tid] = Watt_b[tid] * a[DIM + tid];
        }
        __syncthreads();
        for (int s = 64; s > 0; s >>= 1) {
            if (tid < s) { sc1[tid] += sc1[tid + s]; sc2[tid] += sc2[tid + s]; }
            __syncthreads();
        }
        if (tid == 0) { g_att[2 * DIM] = sc1[0]; g_att[2 * DIM + 1] = sc2[0]; }
    } else {
        int base = (blockIdx.x - 1) * 2048 + tid;
        #pragma unroll
        for (int i = 0; i < 8; i++) {
            int e = base + i * 256;
            int wsel = e >> 14;
            int rem = e & 16383;
            int k = rem >> 7, n = rem & 127;
            float v = wsel ? W2_w[rem] : W1_w[rem];
            __half* img = wsel ? g_W2T : g_W1T;
            img[n * PAD + k] = __float2half(v);
        }
    }
}

// ---------------- K1: scores + fp16 feature table ----------------
__global__ void k_node_scores(const float* __restrict__ feat, int N) {
    int warp = (blockIdx.x * blockDim.x + threadIdx.x) >> 5;
    int lane = threadIdx.x & 31;
    if (warp >= N) return;
    float4 f = *(const float4*)(feat + (size_t)warp * DIM + lane * 4);

    __half2 h0 = __floats2half2_rn(f.x, f.y);
    __half2 h1 = __floats2half2_rn(f.z, f.w);
    uint2 raw;
    raw.x = *(unsigned*)&h0;
    raw.y = *(unsigned*)&h1;
    *(uint2*)(g_featH + (size_t)warp * DIM + lane * 4) = raw;

    float4 v1 = *(const float4*)(g_att + lane * 4);
    float4 v2 = *(const float4*)(g_att + DIM + lane * 4);
    float d1 = f.x * v1.x + f.y * v1.y + f.z * v1.z + f.w * v1.w;
    float d2 = f.x * v2.x + f.y * v2.y + f.z * v2.z + f.w * v2.w;
    #pragma unroll
    for (int o = 16; o > 0; o >>= 1) {
        d1 += __shfl_xor_sync(0xffffffffu, d1, o);
        d2 += __shfl_xor_sync(0xffffffffu, d2, o);
    }
    if (lane == 0) {
        g_s1[warp] = d1 + g_att[2 * DIM];
        g_s2[warp] = d2 + g_att[2 * DIM + 1];
    }
}

// ---------------- K2: fill per-dst buckets (packed u32: halfW<<16 | src) ---------
__global__ void k_fill(const int* __restrict__ idx, int E) {
    int e = blockIdx.x * blockDim.x + threadIdx.x;
    if (e >= E) return;
    int s = idx[e];
    int d = idx[E + e];
    float w = __expf(lrelu(g_s1[s] + g_s2[d]));
    unsigned hw = (unsigned)__half_as_ushort(__float2half_rn(w));
    int pos = atomicAdd(&g_counts[d], 1);
    pos = min(pos, SLOTS - 1);
    g_bucket[(size_t)d * SLOTS + pos] = (hw << 16) | (unsigned)s;
}

// ---------------- K3 (PROFILED): aggregation; LDG.128 half-warp gathers ----------
__global__ void __launch_bounds__(256) k_aggregate(int N) {
    int d = (blockIdx.x * blockDim.x + threadIdx.x) >> 5;
    int lane = threadIdx.x & 31;
    if (d >= N) return;
    int cnt = min(g_counts[d], SLOTS);
    const unsigned* B = g_bucket + (size_t)d * SLOTS;
    int g = lane >> 4, l16 = lane & 15;
    // each lane covers 16B (8 halfs) of the 256B row; group g handles edge j+g
    const char* featB = (const char*)g_featH + l16 * 16;

    // wsum: coalesced strided pass + warp reduction
    float wsum = 0.f;
    for (int j = lane; j < cnt; j += 32)
        wsum += __half2float(__ushort_as_half((unsigned short)(B[j] >> 16)));
    #pragma unroll
    for (int o = 16; o > 0; o >>= 1)
        wsum += __shfl_xor_sync(0xffffffffu, wsum, o);

    __half2 acc[4];
    #pragma unroll
    for (int q = 0; q < 4; q++) acc[q] = __float2half2_rn(0.f);

    int j = 0;
    // 4 edges per iteration (2 per group) for MLP
    for (; j + 4 <= cnt; j += 4) {
        unsigned e0 = B[j + g];
        unsigned e1 = B[j + 2 + g];
        uint4 r0 = *(const uint4*)(featB + ((size_t)(e0 & 0xFFFFu) << 8));
        uint4 r1 = *(const uint4*)(featB + ((size_t)(e1 & 0xFFFFu) << 8));
        unsigned w0u = __byte_perm(e0, e0, 0x3232);
        unsigned w1u = __byte_perm(e1, e1, 0x3232);
        __half2 w0 = *(__half2*)&w0u;
        __half2 w1 = *(__half2*)&w1u;
        acc[0] = __hfma2(w0, *(__half2*)&r0.x, acc[0]);
        acc[1] = __hfma2(w0, *(__half2*)&r0.y, acc[1]);
        acc[2] = __hfma2(w0, *(__half2*)&r0.z, acc[2]);
        acc[3] = __hfma2(w0, *(__half2*)&r0.w, acc[3]);
        acc[0] = __hfma2(w1, *(__half2*)&r1.x, acc[0]);
        acc[1] = __hfma2(w1, *(__half2*)&r1.y, acc[1]);
        acc[2] = __hfma2(w1, *(__half2*)&r1.z, acc[2]);
        acc[3] = __hfma2(w1, *(__half2*)&r1.w, acc[3]);
    }
    for (; j + 2 <= cnt; j += 2) {
        unsigned e = B[j + g];
        uint4 r = *(const uint4*)(featB + ((size_t)(e & 0xFFFFu) << 8));
        unsigned wu = __byte_perm(e, e, 0x3232);
        __half2 w = *(__half2*)&wu;
        acc[0] = __hfma2(w, *(__half2*)&r.x, acc[0]);
        acc[1] = __hfma2(w, *(__half2*)&r.y, acc[1]);
        acc[2] = __hfma2(w, *(__half2*)&r.z, acc[2]);
        acc[3] = __hfma2(w, *(__half2*)&r.w, acc[3]);
    }
    if (j < cnt && g == 0) {  // odd tail: group 0 only
        unsigned e = B[j];
        uint4 r = *(const uint4*)(featB + ((size_t)(e & 0xFFFFu) << 8));
        unsigned wu = __byte_perm(e, e, 0x3232);
        __half2 w = *(__half2*)&wu;
        acc[0] = __hfma2(w, *(__half2*)&r.x, acc[0]);
        acc[1] = __hfma2(w, *(__half2*)&r.y, acc[1]);
        acc[2] = __hfma2(w, *(__half2*)&r.z, acc[2]);
        acc[3] = __hfma2(w, *(__half2*)&r.w, acc[3]);
    }

    // combine the two groups
    #pragma unroll
    for (int q = 0; q < 4; q++) {
        unsigned v = *(unsigned*)&acc[q];
        unsigned o = __shfl_xor_sync(0xffffffffu, v, 16);
        acc[q] = __hadd2(acc[q], *(__half2*)&o);
    }

    if (lane == 0) g_counts[d] = 0;

    if (g == 0) {
        float inv = 1.f / (wsum + 1e-9f);
        uint4 pk;
        unsigned* pku = (unsigned*)&pk;
        #pragma unroll
        for (int q = 0; q < 4; q++) {
            float2 aq = __half22float2(acc[q]);
            __half2 p = __floats2half2_rn(aq.x * inv, aq.y * inv);
            pku[q] = *(unsigned*)&p;
        }
        *(uint4*)(g_aggH + (size_t)d * DIM + l16 * 8) = pk;
    }
}

// ---------------- K4: fused double HMMA GEMM + epilogue ----------------
static constexpr int SM_B1 = 0;
static constexpr int SM_B2 = 512;
static constexpr int SM_A  = 1024;                 // 128*PAD halfs = 34816B
static constexpr int SM_W1 = SM_A + 128 * PAD * 2;
static constexpr int SM_W2 = SM_W1 + 128 * PAD * 2;
static constexpr int SMEMF = SM_W2 + 128 * PAD * 2;  // 105472B

__global__ void __launch_bounds__(512, 1)
k_gemm(const float* __restrict__ feat,
       const float* __restrict__ b1, const float* __restrict__ b2,
       float* __restrict__ out, int N) {
    extern __shared__ char sm[];
    uint32_t smb;
    asm("{ .reg .u64 t; cvta.to.shared.u64 t, %1; cvt.u32.u64 %0, t; }" : "=r"(smb) : "l"(sm));
    int tid = threadIdx.x, wid = tid >> 5, lane = tid & 31;
    int row0 = blockIdx.x * 128;

    {
        const uint4* w1 = (const uint4*)g_W1T;
        const uint4* w2 = (const uint4*)g_W2T;
        uint4* s1p = (uint4*)(sm + SM_W1);
        uint4* s2p = (uint4*)(sm + SM_W2);
        #pragma unroll 4
        for (int i = tid; i < 128 * PAD / 8; i += 512) { s1p[i] = w1[i]; s2p[i] = w2[i]; }
        if (tid < 128) {
            ((float*)(sm + SM_B1))[tid] = b1[tid];
            ((float*)(sm + SM_B2))[tid] = b2[tid];
        }
        #pragma unroll
        for (int i = tid; i < 128 * 16; i += 512) {
            int r = i >> 4, c8 = (i & 15) << 3;
            int gr = row0 + r;
            uint4 v = make_uint4(0u, 0u, 0u, 0u);
            if (gr < N) v = *(const uint4*)(g_aggH + (size_t)gr * DIM + c8);
            *(uint4*)(sm + SM_A + (r * PAD + c8) * 2) = v;
        }
    }
    __syncthreads();

    int m0 = (wid >> 2) * 32, n0 = (wid & 3) * 32;
    int g = lane >> 2, t4 = lane & 3;
    uint32_t aAddrBase = smb + SM_A + ((m0 + (lane & 15)) * PAD + (lane >> 4) * 8) * 2;

    // ---- GEMM1 ----
    float c[2][4][4];
    #pragma unroll
    for (int mi = 0; mi < 2; mi++)
        #pragma unroll
        for (int ni = 0; ni < 4; ni++)
            #pragma unroll
            for (int q = 0; q < 4; q++) c[mi][ni][q] = 0.f;

    #pragma unroll
    for (int kc = 0; kc < 8; kc++) {
        uint32_t a[2][4];
        ldmatrix4(a[0], aAddrBase + kc * 32);
        ldmatrix4(a[1], aAddrBase + 16 * PAD * 2 + kc * 32);
        #pragma unroll
        for (int ni = 0; ni < 4; ni++) {
            const char* bp = sm + SM_W1 + ((n0 + ni * 8 + g) * PAD + kc * 16 + t4 * 2) * 2;
            uint32_t b0 = *(const uint32_t*)bp;
            uint32_t b1r = *(const uint32_t*)(bp + 16);
            mma16816(c[0][ni], a[0], b0, b1r);
            mma16816(c[1][ni], a[1], b0, b1r);
        }
    }

    float hn[2][4][4];
    #pragma unroll
    for (int ni = 0; ni < 4; ni++) {
        int col = n0 + ni * 8 + t4 * 2;
        float bb0 = ((const float*)(sm + SM_B1))[col];
        float bb1 = ((const float*)(sm + SM_B1))[col + 1];
        #pragma unroll
        for (int mi = 0; mi < 2; mi++) {
            hn[mi][ni][0] = c[mi][ni][0] + bb0;
            hn[mi][ni][1] = c[mi][ni][1] + bb1;
            hn[mi][ni][2] = c[mi][ni][2] + bb0;
            hn[mi][ni][3] = c[mi][ni][3] + bb1;
        }
    }
    __syncthreads();

    // ---- prod tile ----
    #pragma unroll
    for (int mi = 0; mi < 2; mi++) {
        int rlo = m0 + mi * 16 + g, rhi = rlo + 8;
        int glo = row0 + rlo, ghi = row0 + rhi;
        #pragma unroll
        for (int ni = 0; ni < 4; ni++) {
            int col = n0 + ni * 8 + t4 * 2;
            float2 flo = make_float2(0.f, 0.f), fhi = make_float2(0.f, 0.f);
            if (glo < N) flo = *(const float2*)(feat + (size_t)glo * DIM + col);
            if (ghi < N) fhi = *(const float2*)(feat + (size_t)ghi * DIM + col);
            __half2 plo = __floats2half2_rn(flo.x * hn[mi][ni][0], flo.y * hn[mi][ni][1]);
            __half2 phi = __floats2half2_rn(fhi.x * hn[mi][ni][2], fhi.y * hn[mi][ni][3]);
            *(__half2*)(sm + SM_A + (rlo * PAD + col) * 2) = plo;
            *(__half2*)(sm + SM_A + (rhi * PAD + col) * 2) = phi;
        }
    }
    __syncthreads();

    // ---- GEMM2 ----
    #pragma unroll
    for (int mi = 0; mi < 2; mi++)
        #pragma unroll
        for (int ni = 0; ni < 4; ni++)
            #pragma unroll
            for (int q = 0; q < 4; q++) c[mi][ni][q] = 0.f;

    #pragma unroll
    for (int kc = 0; kc < 8; kc++) {
        uint32_t a[2][4];
        ldmatrix4(a[0], aAddrBase + kc * 32);
        ldmatrix4(a[1], aAddrBase + 16 * PAD * 2 + kc * 32);
        #pragma unroll
        for (int ni = 0; ni < 4; ni++) {
            const char* bp = sm + SM_W2 + ((n0 + ni * 8 + g) * PAD + kc * 16 + t4 * 2) * 2;
            uint32_t b0 = *(const uint32_t*)bp;
            uint32_t b1r = *(const uint32_t*)(bp + 16);
            mma16816(c[0][ni], a[0], b0, b1r);
            mma16816(c[1][ni], a[1], b0, b1r);
        }
    }

    // ---- epilogue ----
    #pragma unroll
    for (int mi = 0; mi < 2; mi++) {
        int rlo = m0 + mi * 16 + g, rhi = rlo + 8;
        int glo = row0 + rlo, ghi = row0 + rhi;
        #pragma unroll
        for (int ni = 0; ni < 4; ni++) {
            int col = n0 + ni * 8 + t4 * 2;
            float bb0 = ((const float*)(sm + SM_B2))[col];
            float bb1 = ((const float*)(sm + SM_B2))[col + 1];
            if (glo < N) {
                float2 f = *(const float2*)(feat + (size_t)glo * DIM + col);
                float2 o;
                o.x = lrelu(c[mi][ni][0] + bb0 + f.x + hn[mi][ni][0]);
                o.y = lrelu(c[mi][ni][1] + bb1 + f.y + hn[mi][ni][1]);
                *(float2*)(out + (size_t)glo * DIM + col) = o;
            }
            if (ghi < N) {
                float2 f = *(const float2*)(feat + (size_t)ghi * DIM + col);
                float2 o;
                o.x = lrelu(c[mi][ni][2] + bb0 + f.x + hn[mi][ni][2]);
                o.y = lrelu(c[mi][ni][3] + bb1 + f.y + hn[mi][ni][3]);
                *(float2*)(out + (size_t)ghi * DIM + col) = o;
            }
        }
    }
}

// ---------------- launch ----------------
extern "C" void kernel_launch(void* const* d_in, const int* in_sizes, int n_in,
                              void* d_out, int out_size) {
    const int*   indices  = (const int*)d_in[0];
    const float* features = (const float*)d_in[1];
    const float* W1_w   = (const float*)d_in[3];
    const float* W1_b   = (const float*)d_in[4];
    const float* W2_w   = (const float*)d_in[5];
    const float* W2_b   = (const float*)d_in[6];
    const float* Watt_w = (const float*)d_in[7];
    const float* Watt_b = (const float*)d_in[8];
    const float* a_vec  = (const float*)d_in[9];

    int E = in_sizes[0] / 2;
    int N = in_sizes[1] / DIM;

    cudaFuncSetAttribute((const void*)k_gemm,
                         cudaFuncAttributeMaxDynamicSharedMemorySize, SMEMF);

    float* out = (float*)d_out;

    // slot 1
    k_attw<<<17, 256>>>(Watt_w, Watt_b, a_vec, W1_w, W2_w);
    // slot 2
    k_node_scores<<<(N * 32 + 255) / 256, 256>>>(features, N);
    // slot 3
    k_fill<<<(E + 255) / 256, 256>>>(indices, E);
    // slot 4 (profiled)
    k_aggregate<<<(N * 32 + 255) / 256, 256>>>(N);
    // slot 5
    k_gemm<<<(N + 127) / 128, 512, SMEMF>>>(features, W1_b, W2_b, out, N);
}

// round 13
// speedup vs baseline: 1.0338x; 1.0338x over previous
#include <cuda_runtime.h>
#include <cuda_fp16.h>
#include <cstdint>

#define DIM 128
#define MAXN 50176
#define SLOTS 128
#define SLOPE 0.2f
#define PAD 136          // halfs per smem row (272B) — conflict-free ldmatrix
typedef unsigned long long u64;

// ---------------- scratch ----------------
__device__ __align__(16) float  g_att[2 * DIM + 8];
__device__ __align__(16) float  g_s1[MAXN];
__device__ __align__(16) float  g_s2[MAXN];
__device__ __align__(16) __half g_featH[(size_t)MAXN * DIM];
__device__ __align__(16) __half g_aggH[(size_t)MAXN * DIM];     // fp16 aggregate
__device__ __align__(16) int    g_counts[MAXN];                 // self-zeroing
__device__ __align__(16) unsigned g_bucket[(size_t)MAXN * SLOTS]; // (halfW<<16)|src
__device__ __align__(16) __half g_W1T[DIM * PAD];  // W1^T padded: [n][k] = W1[k][n]
__device__ __align__(16) __half g_W2T[DIM * PAD];

__device__ __forceinline__ float lrelu(float x) { return x > 0.f ? x : SLOPE * x; }

__device__ __forceinline__ void mma16816(float* c, const uint32_t* a,
                                         uint32_t b0, uint32_t b1) {
    asm volatile(
        "mma.sync.aligned.m16n8k16.row.col.f32.f16.f16.f32 "
        "{%0,%1,%2,%3}, {%4,%5,%6,%7}, {%8,%9}, {%0,%1,%2,%3};"
        : "+f"(c[0]), "+f"(c[1]), "+f"(c[2]), "+f"(c[3])
        : "r"(a[0]), "r"(a[1]), "r"(a[2]), "r"(a[3]), "r"(b0), "r"(b1));
}
__device__ __forceinline__ void ldmatrix4(uint32_t* a, uint32_t addr) {
    asm volatile("ldmatrix.sync.aligned.m8n8.x4.shared.b16 {%0,%1,%2,%3}, [%4];"
                 : "=r"(a[0]), "=r"(a[1]), "=r"(a[2]), "=r"(a[3]) : "r"(addr));
}

// ---------------- K0: att projection vectors + W^T fp16 tables ----------------
__global__ void k_attw(const float* __restrict__ Watt_w, const float* __restrict__ Watt_b,
                       const float* __restrict__ a,
                       const float* __restrict__ W1_w, const float* __restrict__ W2_w) {
    int tid = threadIdx.x;
    if (blockIdx.x == 0) {
        __shared__ float sc1[DIM], sc2[DIM];
        if (tid < DIM) {
            float v1 = 0.f, v2 = 0.f;
            #pragma unroll 8
            for (int j = 0; j < DIM; j++) {
                float w = Watt_w[tid * DIM + j];
                v1 += w * a[j];
                v2 += w * a[DIM + j];
            }
            g_att[tid] = v1;
            g_att[DIM + tid] = v2;
            sc1[tid] = Watt_b[tid] * a[tid];
            sc2[tid] = Watt_b[tid] * a[DIM + tid];
        }
        __syncthreads();
        for (int s = 64; s > 0; s >>= 1) {
            if (tid < s) { sc1[tid] += sc1[tid + s]; sc2[tid] += sc2[tid + s]; }
            __syncthreads();
        }
        if (tid == 0) { g_att[2 * DIM] = sc1[0]; g_att[2 * DIM + 1] = sc2[0]; }
    } else {
        int base = (blockIdx.x - 1) * 2048 + tid;
        #pragma unroll
        for (int i = 0; i < 8; i++) {
            int e = base + i * 256;
            int wsel = e >> 14;
            int rem = e & 16383;
            int k = rem >> 7, n = rem & 127;
            float v = wsel ? W2_w[rem] : W1_w[rem];
            __half* img = wsel ? g_W2T : g_W1T;
            img[n * PAD + k] = __float2half(v);
        }
    }
}

// ---------------- K1: scores + fp16 feature table ----------------
__global__ void k_node_scores(const float* __restrict__ feat, int N) {
    int warp = (blockIdx.x * blockDim.x + threadIdx.x) >> 5;
    int lane = threadIdx.x & 31;
    if (warp >= N) return;
    float4 f = *(const float4*)(feat + (size_t)warp * DIM + lane * 4);

    __half2 h0 = __floats2half2_rn(f.x, f.y);
    __half2 h1 = __floats2half2_rn(f.z, f.w);
    uint2 raw;
    raw.x = *(unsigned*)&h0;
    raw.y = *(unsigned*)&h1;
    *(uint2*)(g_featH + (size_t)warp * DIM + lane * 4) = raw;

    float4 v1 = *(const float4*)(g_att + lane * 4);
    float4 v2 = *(const float4*)(g_att + DIM + lane * 4);
    float d1 = f.x * v1.x + f.y * v1.y + f.z * v1.z + f.w * v1.w;
    float d2 = f.x * v2.x + f.y * v2.y + f.z * v2.z + f.w * v2.w;
    #pragma unroll
    for (int o = 16; o > 0; o >>= 1) {
        d1 += __shfl_xor_sync(0xffffffffu, d1, o);
        d2 += __shfl_xor_sync(0xffffffffu, d2, o);
    }
    if (lane == 0) {
        g_s1[warp] = d1 + g_att[2 * DIM];
        g_s2[warp] = d2 + g_att[2 * DIM + 1];
    }
}

// ---------------- K2: fill per-dst buckets (packed u32: halfW<<16 | src) ---------
__global__ void k_fill(const int* __restrict__ idx, int E) {
    int e = blockIdx.x * blockDim.x + threadIdx.x;
    if (e >= E) return;
    int s = idx[e];
    int d = idx[E + e];
    float w = __expf(lrelu(g_s1[s] + g_s2[d]));
    unsigned hw = (unsigned)__half_as_ushort(__float2half_rn(w));
    int pos = atomicAdd(&g_counts[d], 1);
    pos = min(pos, SLOTS - 1);
    g_bucket[(size_t)d * SLOTS + pos] = (hw << 16) | (unsigned)s;
}

// ---------------- K3 (PROFILED): aggregation; half-warp LDG.128 + deep MLP ------
__global__ void __launch_bounds__(256) k_aggregate(int N) {
    int d = (blockIdx.x * blockDim.x + threadIdx.x) >> 5;
    int lane = threadIdx.x & 31;
    if (d >= N) return;
    int cnt = min(g_counts[d], SLOTS);
    const unsigned* B = g_bucket + (size_t)d * SLOTS;
    const uint4* B4 = (const uint4*)B;
    int g = lane >> 4, l16 = lane & 15;
    // each lane covers 16B (8 halfs) of the 256B row; two rows per warp-LDG
    const char* featB = (const char*)g_featH + l16 * 16;

    // wsum: coalesced strided pass + warp reduction
    float wsum = 0.f;
    for (int j = lane; j < cnt; j += 32)
        wsum += __half2float(__ushort_as_half((unsigned short)(B[j] >> 16)));
    #pragma unroll
    for (int o = 16; o > 0; o >>= 1)
        wsum += __shfl_xor_sync(0xffffffffu, wsum, o);

    __half2 acc[4];
    #pragma unroll
    for (int q = 0; q < 4; q++) acc[q] = __float2half2_rn(0.f);

    int j = 0;
    // 8 edges/iter: group g handles edges j+4g .. j+4g+3 (one uint4 bucket load,
    // 4 independent LDG.128 gathers -> 8 row-gathers in flight per warp)
    for (; j + 8 <= cnt; j += 8) {
        uint4 qe = B4[(j >> 2) + g];
        uint4 r0 = *(const uint4*)(featB + ((size_t)(qe.x & 0xFFFFu) << 8));
        uint4 r1 = *(const uint4*)(featB + ((size_t)(qe.y & 0xFFFFu) << 8));
        uint4 r2 = *(const uint4*)(featB + ((size_t)(qe.z & 0xFFFFu) << 8));
        uint4 r3 = *(const uint4*)(featB + ((size_t)(qe.w & 0xFFFFu) << 8));
        unsigned w0u = __byte_perm(qe.x, qe.x, 0x3232);
        unsigned w1u = __byte_perm(qe.y, qe.y, 0x3232);
        unsigned w2u = __byte_perm(qe.z, qe.z, 0x3232);
        unsigned w3u = __byte_perm(qe.w, qe.w, 0x3232);
        __half2 w0 = *(__half2*)&w0u, w1 = *(__half2*)&w1u;
        __half2 w2 = *(__half2*)&w2u, w3 = *(__half2*)&w3u;
        acc[0] = __hfma2(w0, *(__half2*)&r0.x, acc[0]);
        acc[1] = __hfma2(w0, *(__half2*)&r0.y, acc[1]);
        acc[2] = __hfma2(w0, *(__half2*)&r0.z, acc[2]);
        acc[3] = __hfma2(w0, *(__half2*)&r0.w, acc[3]);
        acc[0] = __hfma2(w1, *(__half2*)&r1.x, acc[0]);
        acc[1] = __hfma2(w1, *(__half2*)&r1.y, acc[1]);
        acc[2] = __hfma2(w1, *(__half2*)&r1.z, acc[2]);
        acc[3] = __hfma2(w1, *(__half2*)&r1.w, acc[3]);
        acc[0] = __hfma2(w2, *(__half2*)&r2.x, acc[0]);
        acc[1] = __hfma2(w2, *(__half2*)&r2.y, acc[1]);
        acc[2] = __hfma2(w2, *(__half2*)&r2.z, acc[2]);
        acc[3] = __hfma2(w2, *(__half2*)&r2.w, acc[3]);
        acc[0] = __hfma2(w3, *(__half2*)&r3.x, acc[0]);
        acc[1] = __hfma2(w3, *(__half2*)&r3.y, acc[1]);
        acc[2] = __hfma2(w3, *(__half2*)&r3.z, acc[2]);
        acc[3] = __hfma2(w3, *(__half2*)&r3.w, acc[3]);
    }
    // 2 edges/iter tail
    for (; j + 2 <= cnt; j += 2) {
        unsigned e = B[j + g];
        uint4 r = *(const uint4*)(featB + ((size_t)(e & 0xFFFFu) << 8));
        unsigned wu = __byte_perm(e, e, 0x3232);
        __half2 w = *(__half2*)&wu;
        acc[0] = __hfma2(w, *(__half2*)&r.x, acc[0]);
        acc[1] = __hfma2(w, *(__half2*)&r.y, acc[1]);
        acc[2] = __hfma2(w, *(__half2*)&r.z, acc[2]);
        acc[3] = __hfma2(w, *(__half2*)&r.w, acc[3]);
    }
    if (j < cnt && g == 0) {  // odd tail: group 0 only
        unsigned e = B[j];
        uint4 r = *(const uint4*)(featB + ((size_t)(e & 0xFFFFu) << 8));
        unsigned wu = __byte_perm(e, e, 0x3232);
        __half2 w = *(__half2*)&wu;
        acc[0] = __hfma2(w, *(__half2*)&r.x, acc[0]);
        acc[1] = __hfma2(w, *(__half2*)&r.y, acc[1]);
        acc[2] = __hfma2(w, *(__half2*)&r.z, acc[2]);
        acc[3] = __hfma2(w, *(__half2*)&r.w, acc[3]);
    }

    // combine the two groups
    #pragma unroll
    for (int q = 0; q < 4; q++) {
        unsigned v = *(unsigned*)&acc[q];
        unsigned o = __shfl_xor_sync(0xffffffffu, v, 16);
        acc[q] = __hadd2(acc[q], *(__half2*)&o);
    }

    if (lane == 0) g_counts[d] = 0;

    if (g == 0) {
        float inv = 1.f / (wsum + 1e-9f);
        uint4 pk;
        unsigned* pku = (unsigned*)&pk;
        #pragma unroll
        for (int q = 0; q < 4; q++) {
            float2 aq = __half22float2(acc[q]);
            __half2 p = __floats2half2_rn(aq.x * inv, aq.y * inv);
            pku[q] = *(unsigned*)&p;
        }
        *(uint4*)(g_aggH + (size_t)d * DIM + l16 * 8) = pk;
    }
}

// ---------------- K4: fused double HMMA GEMM + epilogue ----------------
static constexpr int SM_B1 = 0;
static constexpr int SM_B2 = 512;
static constexpr int SM_A  = 1024;                 // 128*PAD halfs = 34816B
static constexpr int SM_W1 = SM_A + 128 * PAD * 2;
static constexpr int SM_W2 = SM_W1 + 128 * PAD * 2;
static constexpr int SMEMF = SM_W2 + 128 * PAD * 2;  // 105472B

__global__ void __launch_bounds__(512, 1)
k_gemm(const float* __restrict__ feat,
       const float* __restrict__ b1, const float* __restrict__ b2,
       float* __restrict__ out, int N) {
    extern __shared__ char sm[];
    uint32_t smb;
    asm("{ .reg .u64 t; cvta.to.shared.u64 t, %1; cvt.u32.u64 %0, t; }" : "=r"(smb) : "l"(sm));
    int tid = threadIdx.x, wid = tid >> 5, lane = tid & 31;
    int row0 = blockIdx.x * 128;

    {
        const uint4* w1 = (const uint4*)g_W1T;
        const uint4* w2 = (const uint4*)g_W2T;
        uint4* s1p = (uint4*)(sm + SM_W1);
        uint4* s2p = (uint4*)(sm + SM_W2);
        #pragma unroll 4
        for (int i = tid; i < 128 * PAD / 8; i += 512) { s1p[i] = w1[i]; s2p[i] = w2[i]; }
        if (tid < 128) {
            ((float*)(sm + SM_B1))[tid] = b1[tid];
            ((float*)(sm + SM_B2))[tid] = b2[tid];
        }
        #pragma unroll
        for (int i = tid; i < 128 * 16; i += 512) {
            int r = i >> 4, c8 = (i & 15) << 3;
            int gr = row0 + r;
            uint4 v = make_uint4(0u, 0u, 0u, 0u);
            if (gr < N) v = *(const uint4*)(g_aggH + (size_t)gr * DIM + c8);
            *(uint4*)(sm + SM_A + (r * PAD + c8) * 2) = v;
        }
    }
    __syncthreads();

    int m0 = (wid >> 2) * 32, n0 = (wid & 3) * 32;
    int g = lane >> 2, t4 = lane & 3;
    uint32_t aAddrBase = smb + SM_A + ((m0 + (lane & 15)) * PAD + (lane >> 4) * 8) * 2;

    // ---- GEMM1 ----
    float c[2][4][4];
    #pragma unroll
    for (int mi = 0; mi < 2; mi++)
        #pragma unroll
        for (int ni = 0; ni < 4; ni++)
            #pragma unroll
            for (int q = 0; q < 4; q++) c[mi][ni][q] = 0.f;

    #pragma unroll
    for (int kc = 0; kc < 8; kc++) {
        uint32_t a[2][4];
        ldmatrix4(a[0], aAddrBase + kc * 32);
        ldmatrix4(a[1], aAddrBase + 16 * PAD * 2 + kc * 32);
        #pragma unroll
        for (int ni = 0; ni < 4; ni++) {
            const char* bp = sm + SM_W1 + ((n0 + ni * 8 + g) * PAD + kc * 16 + t4 * 2) * 2;
            uint32_t b0 = *(const uint32_t*)bp;
            uint32_t b1r = *(const uint32_t*)(bp + 16);
            mma16816(c[0][ni], a[0], b0, b1r);
            mma16816(c[1][ni], a[1], b0, b1r);
        }
    }

    float hn[2][4][4];
    #pragma unroll
    for (int ni = 0; ni < 4; ni++) {
        int col = n0 + ni * 8 + t4 * 2;
        float bb0 = ((const float*)(sm + SM_B1))[col];
        float bb1 = ((const float*)(sm + SM_B1))[col + 1];
        #pragma unroll
        for (int mi = 0; mi < 2; mi++) {
            hn[mi][ni][0] = c[mi][ni][0] + bb0;
            hn[mi][ni][1] = c[mi][ni][1] + bb1;
            hn[mi][ni][2] = c[mi][ni][2] + bb0;
            hn[mi][ni][3] = c[mi][ni][3] + bb1;
        }
    }
    __syncthreads();

    // ---- prod tile ----
    #pragma unroll
    for (int mi = 0; mi < 2; mi++) {
        int rlo = m0 + mi * 16 + g, rhi = rlo + 8;
        int glo = row0 + rlo, ghi = row0 + rhi;
        #pragma unroll
        for (int ni = 0; ni < 4; ni++) {
            int col = n0 + ni * 8 + t4 * 2;
            float2 flo = make_float2(0.f, 0.f), fhi = make_float2(0.f, 0.f);
            if (glo < N) flo = *(const float2*)(feat + (size_t)glo * DIM + col);
            if (ghi < N) fhi = *(const float2*)(feat + (size_t)ghi * DIM + col);
            __half2 plo = __floats2half2_rn(flo.x * hn[mi][ni][0], flo.y * hn[mi][ni][1]);
            __half2 phi = __floats2half2_rn(fhi.x * hn[mi][ni][2], fhi.y * hn[mi][ni][3]);
            *(__half2*)(sm + SM_A + (rlo * PAD + col) * 2) = plo;
            *(__half2*)(sm + SM_A + (rhi * PAD + col) * 2) = phi;
        }
    }
    __syncthreads();

    // ---- GEMM2 ----
    #pragma unroll
    for (int mi = 0; mi < 2; mi++)
        #pragma unroll
        for (int ni = 0; ni < 4; ni++)
            #pragma unroll
            for (int q = 0; q < 4; q++) c[mi][ni][q] = 0.f;

    #pragma unroll
    for (int kc = 0; kc < 8; kc++) {
        uint32_t a[2][4];
        ldmatrix4(a[0], aAddrBase + kc * 32);
        ldmatrix4(a[1], aAddrBase + 16 * PAD * 2 + kc * 32);
        #pragma unroll
        for (int ni = 0; ni < 4; ni++) {
            const char* bp = sm + SM_W2 + ((n0 + ni * 8 + g) * PAD + kc * 16 + t4 * 2) * 2;
            uint32_t b0 = *(const uint32_t*)bp;
            uint32_t b1r = *(const uint32_t*)(bp + 16);
            mma16816(c[0][ni], a[0], b0, b1r);
            mma16816(c[1][ni], a[1], b0, b1r);
        }
    }

    // ---- epilogue ----
    #pragma unroll
    for (int mi = 0; mi < 2; mi++) {
        int rlo = m0 + mi * 16 + g, rhi = rlo + 8;
        int glo = row0 + rlo, ghi = row0 + rhi;
        #pragma unroll
        for (int ni = 0; ni < 4; ni++) {
            int col = n0 + ni * 8 + t4 * 2;
            float bb0 = ((const float*)(sm + SM_B2))[col];
            float bb1 = ((const float*)(sm + SM_B2))[col + 1];
            if (glo < N) {
                float2 f = *(const float2*)(feat + (size_t)glo * DIM + col);
                float2 o;
                o.x = lrelu(c[mi][ni][0] + bb0 + f.x + hn[mi][ni][0]);
                o.y = lrelu(c[mi][ni][1] + bb1 + f.y + hn[mi][ni][1]);
                *(float2*)(out + (size_t)glo * DIM + col) = o;
            }
            if (ghi < N) {
                float2 f = *(const float2*)(feat + (size_t)ghi * DIM + col);
                float2 o;
                o.x = lrelu(c[mi][ni][2] + bb0 + f.x + hn[mi][ni][2]);
                o.y = lrelu(c[mi][ni][3] + bb1 + f.y + hn[mi][ni][3]);
                *(float2*)(out + (size_t)ghi * DIM + col) = o;
            }
        }
    }
}

// ---------------- launch ----------------
extern "C" void kernel_launch(void* const* d_in, const int* in_sizes, int n_in,
                              void* d_out, int out_size) {
    const int*   indices  = (const int*)d_in[0];
    const float* features = (const float*)d_in[1];
    const float* W1_w   = (const float*)d_in[3];
    const float* W1_b   = (const float*)d_in[4];
    const float* W2_w   = (const float*)d_in[5];
    const float* W2_b   = (const float*)d_in[6];
    const float* Watt_w = (const float*)d_in[7];
    const float* Watt_b = (const float*)d_in[8];
    const float* a_vec  = (const float*)d_in[9];

    int E = in_sizes[0] / 2;
    int N = in_sizes[1] / DIM;

    cudaFuncSetAttribute((const void*)k_gemm,
                         cudaFuncAttributeMaxDynamicSharedMemorySize, SMEMF);

    float* out = (float*)d_out;

    // slot 1
    k_attw<<<17, 256>>>(Watt_w, Watt_b, a_vec, W1_w, W2_w);
    // slot 2
    k_node_scores<<<(N * 32 + 255) / 256, 256>>>(features, N);
    // slot 3
    k_fill<<<(E + 255) / 256, 256>>>(indices, E);
    // slot 4 (profiled)
    k_aggregate<<<(N * 32 + 255) / 256, 256>>>(N);
    // slot 5
    k_gemm<<<(N + 127) / 128, 512, SMEMF>>>(features, W1_b, W2_b, out, N);
}

// round 14
// speedup vs baseline: 1.0514x; 1.0170x over previous
#include <cuda_runtime.h>
#include <cuda_fp16.h>
#include <cstdint>

#define DIM 128
#define MAXN 50176
#define SLOTS 128
#define SLOPE 0.2f
#define PAD 136          // halfs per smem row (272B) — conflict-free ldmatrix
typedef unsigned long long u64;

// ---------------- scratch ----------------
__device__ __align__(16) float  g_att[2 * DIM + 8];
__device__ __align__(16) float  g_s1[MAXN];
__device__ __align__(16) float  g_s2[MAXN];
__device__ __align__(16) __half g_featH[(size_t)MAXN * DIM];
__device__ __align__(16) __half g_aggH[(size_t)MAXN * DIM];     // fp16 aggregate
__device__ __align__(16) int    g_counts[MAXN];                 // self-zeroing
__device__ __align__(16) unsigned g_bucket[(size_t)MAXN * SLOTS]; // (halfW<<16)|src
__device__ __align__(16) __half g_W1T[DIM * PAD];  // W1^T padded: [n][k] = W1[k][n]
__device__ __align__(16) __half g_W2T[DIM * PAD];

__device__ __forceinline__ float lrelu(float x) { return x > 0.f ? x : SLOPE * x; }

__device__ __forceinline__ void mma16816(float* c, const uint32_t* a,
                                         uint32_t b0, uint32_t b1) {
    asm volatile(
        "mma.sync.aligned.m16n8k16.row.col.f32.f16.f16.f32 "
        "{%0,%1,%2,%3}, {%4,%5,%6,%7}, {%8,%9}, {%0,%1,%2,%3};"
        : "+f"(c[0]), "+f"(c[1]), "+f"(c[2]), "+f"(c[3])
        : "r"(a[0]), "r"(a[1]), "r"(a[2]), "r"(a[3]), "r"(b0), "r"(b1));
}
__device__ __forceinline__ void ldmatrix4(uint32_t* a, uint32_t addr) {
    asm volatile("ldmatrix.sync.aligned.m8n8.x4.shared.b16 {%0,%1,%2,%3}, [%4];"
                 : "=r"(a[0]), "=r"(a[1]), "=r"(a[2]), "=r"(a[3]) : "r"(addr));
}

// ---------------- K0: att projection vectors + W^T fp16 tables ----------------
__global__ void k_attw(const float* __restrict__ Watt_w, const float* __restrict__ Watt_b,
                       const float* __restrict__ a,
                       const float* __restrict__ W1_w, const float* __restrict__ W2_w) {
    int tid = threadIdx.x;
    if (blockIdx.x == 0) {
        __shared__ float sc1[DIM], sc2[DIM];
        if (tid < DIM) {
            float v1 = 0.f, v2 = 0.f;
            #pragma unroll 8
            for (int j = 0; j < DIM; j++) {
                float w = Watt_w[tid * DIM + j];
                v1 += w * a[j];
                v2 += w * a[DIM + j];
            }
            g_att[tid] = v1;
            g_att[DIM + tid] = v2;
            sc1[tid] = Watt_b[tid] * a[tid];
            sc2[tid] = Watt_b[tid] * a[DIM + tid];
        }
        __syncthreads();
        for (int s = 64; s > 0; s >>= 1) {
            if (tid < s) { sc1[tid] += sc1[tid + s]; sc2[tid] += sc2[tid + s]; }
            __syncthreads();
        }
        if (tid == 0) { g_att[2 * DIM] = sc1[0]; g_att[2 * DIM + 1] = sc2[0]; }
    } else {
        int base = (blockIdx.x - 1) * 2048 + tid;
        #pragma unroll
        for (int i = 0; i < 8; i++) {
            int e = base + i * 256;
            int wsel = e >> 14;
            int rem = e & 16383;
            int k = rem >> 7, n = rem & 127;
            float v = wsel ? W2_w[rem] : W1_w[rem];
            __half* img = wsel ? g_W2T : g_W1T;
            img[n * PAD + k] = __float2half(v);
        }
    }
}

// ---------------- K1: scores + fp16 feature table ----------------
__global__ void k_node_scores(const float* __restrict__ feat, int N) {
    int warp = (blockIdx.x * blockDim.x + threadIdx.x) >> 5;
    int lane = threadIdx.x & 31;
    if (warp >= N) return;
    float4 f = *(const float4*)(feat + (size_t)warp * DIM + lane * 4);

    __half2 h0 = __floats2half2_rn(f.x, f.y);
    __half2 h1 = __floats2half2_rn(f.z, f.w);
    uint2 raw;
    raw.x = *(unsigned*)&h0;
    raw.y = *(unsigned*)&h1;
    *(uint2*)(g_featH + (size_t)warp * DIM + lane * 4) = raw;

    float4 v1 = *(const float4*)(g_att + lane * 4);
    float4 v2 = *(const float4*)(g_att + DIM + lane * 4);
    float d1 = f.x * v1.x + f.y * v1.y + f.z * v1.z + f.w * v1.w;
    float d2 = f.x * v2.x + f.y * v2.y + f.z * v2.z + f.w * v2.w;
    #pragma unroll
    for (int o = 16; o > 0; o >>= 1) {
        d1 += __shfl_xor_sync(0xffffffffu, d1, o);
        d2 += __shfl_xor_sync(0xffffffffu, d2, o);
    }
    if (lane == 0) {
        g_s1[warp] = d1 + g_att[2 * DIM];
        g_s2[warp] = d2 + g_att[2 * DIM + 1];
    }
}

// ---------------- K2: fill per-dst buckets; 2 edges/thread -----------------------
__global__ void k_fill(const int* __restrict__ idx, int E) {
    int e2 = (blockIdx.x * blockDim.x + threadIdx.x) * 2;
    if (e2 >= E) return;
    int2 ss = *(const int2*)(idx + e2);
    int2 dd = *(const int2*)(idx + E + e2);

    {
        float w = __expf(lrelu(g_s1[ss.x] + g_s2[dd.x]));
        unsigned hw = (unsigned)__half_as_ushort(__float2half_rn(w));
        int pos = atomicAdd(&g_counts[dd.x], 1);
        pos = min(pos, SLOTS - 1);
        g_bucket[(size_t)dd.x * SLOTS + pos] = (hw << 16) | (unsigned)ss.x;
    }
    if (e2 + 1 < E) {
        float w = __expf(lrelu(g_s1[ss.y] + g_s2[dd.y]));
        unsigned hw = (unsigned)__half_as_ushort(__float2half_rn(w));
        int pos = atomicAdd(&g_counts[dd.y], 1);
        pos = min(pos, SLOTS - 1);
        g_bucket[(size_t)dd.y * SLOTS + pos] = (hw << 16) | (unsigned)ss.y;
    }
}

// ---------------- K3 (PROFILED): aggregation; half-warp LDG.128 + deep MLP ------
__global__ void __launch_bounds__(256) k_aggregate(int N) {
    int d = (blockIdx.x * blockDim.x + threadIdx.x) >> 5;
    int lane = threadIdx.x & 31;
    if (d >= N) return;
    int cnt = min(g_counts[d], SLOTS);
    const unsigned* B = g_bucket + (size_t)d * SLOTS;
    const uint4* B4 = (const uint4*)B;
    int g = lane >> 4, l16 = lane & 15;
    const char* featB = (const char*)g_featH + l16 * 16;

    // wsum: coalesced strided pass + warp reduction
    float wsum = 0.f;
    for (int j = lane; j < cnt; j += 32)
        wsum += __half2float(__ushort_as_half((unsigned short)(B[j] >> 16)));
    #pragma unroll
    for (int o = 16; o > 0; o >>= 1)
        wsum += __shfl_xor_sync(0xffffffffu, wsum, o);

    __half2 acc[4];
    #pragma unroll
    for (int q = 0; q < 4; q++) acc[q] = __float2half2_rn(0.f);

    int j = 0;
    for (; j + 8 <= cnt; j += 8) {
        uint4 qe = B4[(j >> 2) + g];
        uint4 r0 = *(const uint4*)(featB + ((size_t)(qe.x & 0xFFFFu) << 8));
        uint4 r1 = *(const uint4*)(featB + ((size_t)(qe.y & 0xFFFFu) << 8));
        uint4 r2 = *(const uint4*)(featB + ((size_t)(qe.z & 0xFFFFu) << 8));
        uint4 r3 = *(const uint4*)(featB + ((size_t)(qe.w & 0xFFFFu) << 8));
        unsigned w0u = __byte_perm(qe.x, qe.x, 0x3232);
        unsigned w1u = __byte_perm(qe.y, qe.y, 0x3232);
        unsigned w2u = __byte_perm(qe.z, qe.z, 0x3232);
        unsigned w3u = __byte_perm(qe.w, qe.w, 0x3232);
        __half2 w0 = *(__half2*)&w0u, w1 = *(__half2*)&w1u;
        __half2 w2 = *(__half2*)&w2u, w3 = *(__half2*)&w3u;
        acc[0] = __hfma2(w0, *(__half2*)&r0.x, acc[0]);
        acc[1] = __hfma2(w0, *(__half2*)&r0.y, acc[1]);
        acc[2] = __hfma2(w0, *(__half2*)&r0.z, acc[2]);
        acc[3] = __hfma2(w0, *(__half2*)&r0.w, acc[3]);
        acc[0] = __hfma2(w1, *(__half2*)&r1.x, acc[0]);
        acc[1] = __hfma2(w1, *(__half2*)&r1.y, acc[1]);
        acc[2] = __hfma2(w1, *(__half2*)&r1.z, acc[2]);
        acc[3] = __hfma2(w1, *(__half2*)&r1.w, acc[3]);
        acc[0] = __hfma2(w2, *(__half2*)&r2.x, acc[0]);
        acc[1] = __hfma2(w2, *(__half2*)&r2.y, acc[1]);
        acc[2] = __hfma2(w2, *(__half2*)&r2.z, acc[2]);
        acc[3] = __hfma2(w2, *(__half2*)&r2.w, acc[3]);
        acc[0] = __hfma2(w3, *(__half2*)&r3.x, acc[0]);
        acc[1] = __hfma2(w3, *(__half2*)&r3.y, acc[1]);
        acc[2] = __hfma2(w3, *(__half2*)&r3.z, acc[2]);
        acc[3] = __hfma2(w3, *(__half2*)&r3.w, acc[3]);
    }
    for (; j + 2 <= cnt; j += 2) {
        unsigned e = B[j + g];
        uint4 r = *(const uint4*)(featB + ((size_t)(e & 0xFFFFu) << 8));
        unsigned wu = __byte_perm(e, e, 0x3232);
        __half2 w = *(__half2*)&wu;
        acc[0] = __hfma2(w, *(__half2*)&r.x, acc[0]);
        acc[1] = __hfma2(w, *(__half2*)&r.y, acc[1]);
        acc[2] = __hfma2(w, *(__half2*)&r.z, acc[2]);
        acc[3] = __hfma2(w, *(__half2*)&r.w, acc[3]);
    }
    if (j < cnt && g == 0) {
        unsigned e = B[j];
        uint4 r = *(const uint4*)(featB + ((size_t)(e & 0xFFFFu) << 8));
        unsigned wu = __byte_perm(e, e, 0x3232);
        __half2 w = *(__half2*)&wu;
        acc[0] = __hfma2(w, *(__half2*)&r.x, acc[0]);
        acc[1] = __hfma2(w, *(__half2*)&r.y, acc[1]);
        acc[2] = __hfma2(w, *(__half2*)&r.z, acc[2]);
        acc[3] = __hfma2(w, *(__half2*)&r.w, acc[3]);
    }

    #pragma unroll
    for (int q = 0; q < 4; q++) {
        unsigned v = *(unsigned*)&acc[q];
        unsigned o = __shfl_xor_sync(0xffffffffu, v, 16);
        acc[q] = __hadd2(acc[q], *(__half2*)&o);
    }

    if (lane == 0) g_counts[d] = 0;

    if (g == 0) {
        float inv = 1.f / (wsum + 1e-9f);
        uint4 pk;
        unsigned* pku = (unsigned*)&pk;
        #pragma unroll
        for (int q = 0; q < 4; q++) {
            float2 aq = __half22float2(acc[q]);
            __half2 p = __floats2half2_rn(aq.x * inv, aq.y * inv);
            pku[q] = *(unsigned*)&p;
        }
        *(uint4*)(g_aggH + (size_t)d * DIM + l16 * 8) = pk;
    }
}

// ---------------- K4: fused double HMMA GEMM + epilogue ----------------
static constexpr int SM_B1 = 0;
static constexpr int SM_B2 = 512;
static constexpr int SM_A  = 1024;                 // 128*PAD halfs = 34816B
static constexpr int SM_W1 = SM_A + 128 * PAD * 2;
static constexpr int SM_W2 = SM_W1 + 128 * PAD * 2;
static constexpr int SMEMF = SM_W2 + 128 * PAD * 2;  // 105472B

__global__ void __launch_bounds__(512, 1)
k_gemm(const float* __restrict__ feat,
       const float* __restrict__ b1, const float* __restrict__ b2,
       float* __restrict__ out, int N) {
    extern __shared__ char sm[];
    uint32_t smb;
    asm("{ .reg .u64 t; cvta.to.shared.u64 t, %1; cvt.u32.u64 %0, t; }" : "=r"(smb) : "l"(sm));
    int tid = threadIdx.x, wid = tid >> 5, lane = tid & 31;
    int row0 = blockIdx.x * 128;

    int m0 = (wid >> 2) * 32, n0 = (wid & 3) * 32;
    int g = lane >> 2, t4 = lane & 3;

    // ---- prefetch feat for prod-tile + epilogue (independent of smem; overlaps
    //      weight staging AND GEMM1's MMA latency) ----
    float2 fC[2][2][4];  // [mi][lo/hi][ni]
    #pragma unroll
    for (int mi = 0; mi < 2; mi++) {
        int rlo = m0 + mi * 16 + g, rhi = rlo + 8;
        int glo = row0 + rlo, ghi = row0 + rhi;
        #pragma unroll
        for (int ni = 0; ni < 4; ni++) {
            int col = n0 + ni * 8 + t4 * 2;
            fC[mi][0][ni] = make_float2(0.f, 0.f);
            fC[mi][1][ni] = make_float2(0.f, 0.f);
            if (glo < N) fC[mi][0][ni] = *(const float2*)(feat + (size_t)glo * DIM + col);
            if (ghi < N) fC[mi][1][ni] = *(const float2*)(feat + (size_t)ghi * DIM + col);
        }
    }

    {
        const uint4* w1 = (const uint4*)g_W1T;
        const uint4* w2 = (const uint4*)g_W2T;
        uint4* s1p = (uint4*)(sm + SM_W1);
        uint4* s2p = (uint4*)(sm + SM_W2);
        #pragma unroll 4
        for (int i = tid; i < 128 * PAD / 8; i += 512) { s1p[i] = w1[i]; s2p[i] = w2[i]; }
        if (tid < 128) {
            ((float*)(sm + SM_B1))[tid] = b1[tid];
            ((float*)(sm + SM_B2))[tid] = b2[tid];
        }
        #pragma unroll
        for (int i = tid; i < 128 * 16; i += 512) {
            int r = i >> 4, c8 = (i & 15) << 3;
            int gr = row0 + r;
            uint4 v = make_uint4(0u, 0u, 0u, 0u);
            if (gr < N) v = *(const uint4*)(g_aggH + (size_t)gr * DIM + c8);
            *(uint4*)(sm + SM_A + (r * PAD + c8) * 2) = v;
        }
    }
    __syncthreads();

    uint32_t aAddrBase = smb + SM_A + ((m0 + (lane & 15)) * PAD + (lane >> 4) * 8) * 2;

    // ---- GEMM1 ----
    float c[2][4][4];
    #pragma unroll
    for (int mi = 0; mi < 2; mi++)
        #pragma unroll
        for (int ni = 0; ni < 4; ni++)
            #pragma unroll
            for (int q = 0; q < 4; q++) c[mi][ni][q] = 0.f;

    #pragma unroll
    for (int kc = 0; kc < 8; kc++) {
        uint32_t a[2][4];
        ldmatrix4(a[0], aAddrBase + kc * 32);
        ldmatrix4(a[1], aAddrBase + 16 * PAD * 2 + kc * 32);
        #pragma unroll
        for (int ni = 0; ni < 4; ni++) {
            const char* bp = sm + SM_W1 + ((n0 + ni * 8 + g) * PAD + kc * 16 + t4 * 2) * 2;
            uint32_t b0 = *(const uint32_t*)bp;
            uint32_t b1r = *(const uint32_t*)(bp + 16);
            mma16816(c[0][ni], a[0], b0, b1r);
            mma16816(c[1][ni], a[1], b0, b1r);
        }
    }

    float hn[2][4][4];
    #pragma unroll
    for (int ni = 0; ni < 4; ni++) {
        int col = n0 + ni * 8 + t4 * 2;
        float bb0 = ((const float*)(sm + SM_B1))[col];
        float bb1 = ((const float*)(sm + SM_B1))[col + 1];
        #pragma unroll
        for (int mi = 0; mi < 2; mi++) {
            hn[mi][ni][0] = c[mi][ni][0] + bb0;
            hn[mi][ni][1] = c[mi][ni][1] + bb1;
            hn[mi][ni][2] = c[mi][ni][2] + bb0;
            hn[mi][ni][3] = c[mi][ni][3] + bb1;
        }
    }
    __syncthreads();

    // ---- prod tile (uses cached feat) ----
    #pragma unroll
    for (int mi = 0; mi < 2; mi++) {
        int rlo = m0 + mi * 16 + g, rhi = rlo + 8;
        #pragma unroll
        for (int ni = 0; ni < 4; ni++) {
            int col = n0 + ni * 8 + t4 * 2;
            float2 flo = fC[mi][0][ni], fhi = fC[mi][1][ni];
            __half2 plo = __floats2half2_rn(flo.x * hn[mi][ni][0], flo.y * hn[mi][ni][1]);
            __half2 phi = __floats2half2_rn(fhi.x * hn[mi][ni][2], fhi.y * hn[mi][ni][3]);
            *(__half2*)(sm + SM_A + (rlo * PAD + col) * 2) = plo;
            *(__half2*)(sm + SM_A + (rhi * PAD + col) * 2) = phi;
        }
    }
    __syncthreads();

    // ---- GEMM2 ----
    #pragma unroll
    for (int mi = 0; mi < 2; mi++)
        #pragma unroll
        for (int ni = 0; ni < 4; ni++)
            #pragma unroll
            for (int q = 0; q < 4; q++) c[mi][ni][q] = 0.f;

    #pragma unroll
    for (int kc = 0; kc < 8; kc++) {
        uint32_t a[2][4];
        ldmatrix4(a[0], aAddrBase + kc * 32);
        ldmatrix4(a[1], aAddrBase + 16 * PAD * 2 + kc * 32);
        #pragma unroll
        for (int ni = 0; ni < 4; ni++) {
            const char* bp = sm + SM_W2 + ((n0 + ni * 8 + g) * PAD + kc * 16 + t4 * 2) * 2;
            uint32_t b0 = *(const uint32_t*)bp;
            uint32_t b1r = *(const uint32_t*)(bp + 16);
            mma16816(c[0][ni], a[0], b0, b1r);
            mma16816(c[1][ni], a[1], b0, b1r);
        }
    }

    // ---- epilogue (uses cached feat) ----
    #pragma unroll
    for (int mi = 0; mi < 2; mi++) {
        int rlo = m0 + mi * 16 + g, rhi = rlo + 8;
        int glo = row0 + rlo, ghi = row0 + rhi;
        #pragma unroll
        for (int ni = 0; ni < 4; ni++) {
            int col = n0 + ni * 8 + t4 * 2;
            float bb0 = ((const float*)(sm + SM_B2))[col];
            float bb1 = ((const float*)(sm + SM_B2))[col + 1];
            if (glo < N) {
                float2 f = fC[mi][0][ni];
                float2 o;
                o.x = lrelu(c[mi][ni][0] + bb0 + f.x + hn[mi][ni][0]);
                o.y = lrelu(c[mi][ni][1] + bb1 + f.y + hn[mi][ni][1]);
                *(float2*)(out + (size_t)glo * DIM + col) = o;
            }
            if (ghi < N) {
                float2 f = fC[mi][1][ni];
                float2 o;
                o.x = lrelu(c[mi][ni][2] + bb0 + f.x + hn[mi][ni][2]);
                o.y = lrelu(c[mi][ni][3] + bb1 + f.y + hn[mi][ni][3]);
                *(float2*)(out + (size_t)ghi * DIM + col) = o;
            }
        }
    }
}

// ---------------- launch ----------------
extern "C" void kernel_launch(void* const* d_in, const int* in_sizes, int n_in,
                              void* d_out, int out_size) {
    const int*   indices  = (const int*)d_in[0];
    const float* features = (const float*)d_in[1];
    const float* W1_w   = (const float*)d_in[3];
    const float* W1_b   = (const float*)d_in[4];
    const float* W2_w   = (const float*)d_in[5];
    const float* W2_b   = (const float*)d_in[6];
    const float* Watt_w = (const float*)d_in[7];
    const float* Watt_b = (const float*)d_in[8];
    const float* a_vec  = (const float*)d_in[9];

    int E = in_sizes[0] / 2;
    int N = in_sizes[1] / DIM;

    cudaFuncSetAttribute((const void*)k_gemm,
                         cudaFuncAttributeMaxDynamicSharedMemorySize, SMEMF);

    float* out = (float*)d_out;

    // slot 1
    k_attw<<<17, 256>>>(Watt_w, Watt_b, a_vec, W1_w, W2_w);
    // slot 2
    k_node_scores<<<(N * 32 + 255) / 256, 256>>>(features, N);
    // slot 3 (2 edges per thread)
    k_fill<<<((E + 1) / 2 + 255) / 256, 256>>>(indices, E);
    // slot 4 (profiled)
    k_aggregate<<<(N * 32 + 255) / 256, 256>>>(N);
    // slot 5
    k_gemm<<<(N + 127) / 128, 512, SMEMF>>>(features, W1_b, W2_b, out, N);
}

// round 15
// speedup vs baseline: 1.0810x; 1.0281x over previous
#include <cuda_runtime.h>
#include <cuda_fp16.h>
#include <cstdint>

#define DIM 128
#define MAXN 50176
#define SLOTS 128
#define SLOPE 0.2f
#define PAD 136          // halfs per smem row (272B) — conflict-free ldmatrix
typedef unsigned long long u64;

// ---------------- scratch ----------------
__device__ __align__(16) float  g_att[2 * DIM + 8];
__device__ __align__(16) float  g_s1[MAXN];
__device__ __align__(16) float  g_s2[MAXN];
__device__ __align__(16) __half g_featH[(size_t)MAXN * DIM];
__device__ __align__(16) __half g_aggH[(size_t)MAXN * DIM];     // fp16 aggregate
__device__ __align__(16) int    g_counts[MAXN];                 // self-zeroing
__device__ __align__(16) unsigned g_bucket[(size_t)MAXN * SLOTS]; // (halfW<<16)|src
__device__ __align__(16) __half g_W1T[DIM * PAD];  // W1^T padded: [n][k] = W1[k][n]
__device__ __align__(16) __half g_W2T[DIM * PAD];

__device__ __forceinline__ float lrelu(float x) { return x > 0.f ? x : SLOPE * x; }

__device__ __forceinline__ void mma16816(float* c, const uint32_t* a,
                                         uint32_t b0, uint32_t b1) {
    asm volatile(
        "mma.sync.aligned.m16n8k16.row.col.f32.f16.f16.f32 "
        "{%0,%1,%2,%3}, {%4,%5,%6,%7}, {%8,%9}, {%0,%1,%2,%3};"
        : "+f"(c[0]), "+f"(c[1]), "+f"(c[2]), "+f"(c[3])
        : "r"(a[0]), "r"(a[1]), "r"(a[2]), "r"(a[3]), "r"(b0), "r"(b1));
}
__device__ __forceinline__ void ldmatrix4(uint32_t* a, uint32_t addr) {
    asm volatile("ldmatrix.sync.aligned.m8n8.x4.shared.b16 {%0,%1,%2,%3}, [%4];"
                 : "=r"(a[0]), "=r"(a[1]), "=r"(a[2]), "=r"(a[3]) : "r"(addr));
}

// ---------------- K0: att projection vectors + W^T fp16 tables ----------------
__global__ void k_attw(const float* __restrict__ Watt_w, const float* __restrict__ Watt_b,
                       const float* __restrict__ a,
                       const float* __restrict__ W1_w, const float* __restrict__ W2_w) {
    int tid = threadIdx.x;
    if (blockIdx.x == 0) {
        __shared__ float sc1[DIM], sc2[DIM];
        if (tid < DIM) {
            float v1 = 0.f, v2 = 0.f;
            #pragma unroll 8
            for (int j = 0; j < DIM; j++) {
                float w = Watt_w[tid * DIM + j];
                v1 += w * a[j];
                v2 += w * a[DIM + j];
            }
            g_att[tid] = v1;
            g_att[DIM + tid] = v2;
            sc1[tid] = Watt_b[tid] * a[tid];
            sc2[tid] = Watt_b[tid] * a[DIM + tid];
        }
        __syncthreads();
        for (int s = 64; s > 0; s >>= 1) {
            if (tid < s) { sc1[tid] += sc1[tid + s]; sc2[tid] += sc2[tid + s]; }
            __syncthreads();
        }
        if (tid == 0) { g_att[2 * DIM] = sc1[0]; g_att[2 * DIM + 1] = sc2[0]; }
    } else {
        int base = (blockIdx.x - 1) * 2048 + tid;
        #pragma unroll
        for (int i = 0; i < 8; i++) {
            int e = base + i * 256;
            int wsel = e >> 14;
            int rem = e & 16383;
            int k = rem >> 7, n = rem & 127;
            float v = wsel ? W2_w[rem] : W1_w[rem];
            __half* img = wsel ? g_W2T : g_W1T;
            img[n * PAD + k] = __float2half(v);
        }
    }
}

// ---------------- K1: scores + fp16 feature table (PDL after attw) --------------
__global__ void k_node_scores(const float* __restrict__ feat, int N) {
    int warp = (blockIdx.x * blockDim.x + threadIdx.x) >> 5;
    int lane = threadIdx.x & 31;
    if (warp >= N) {
        cudaGridDependencySynchronize();
        return;
    }
    // independent prologue: feat load + fp16 table emit
    float4 f = *(const float4*)(feat + (size_t)warp * DIM + lane * 4);
    __half2 h0 = __floats2half2_rn(f.x, f.y);
    __half2 h1 = __floats2half2_rn(f.z, f.w);
    uint2 raw;
    raw.x = *(unsigned*)&h0;
    raw.y = *(unsigned*)&h1;
    *(uint2*)(g_featH + (size_t)warp * DIM + lane * 4) = raw;

    cudaGridDependencySynchronize();  // wait for g_att

    float4 v1 = *(const float4*)(g_att + lane * 4);
    float4 v2 = *(const float4*)(g_att + DIM + lane * 4);
    float d1 = f.x * v1.x + f.y * v1.y + f.z * v1.z + f.w * v1.w;
    float d2 = f.x * v2.x + f.y * v2.y + f.z * v2.z + f.w * v2.w;
    #pragma unroll
    for (int o = 16; o > 0; o >>= 1) {
        d1 += __shfl_xor_sync(0xffffffffu, d1, o);
        d2 += __shfl_xor_sync(0xffffffffu, d2, o);
    }
    if (lane == 0) {
        g_s1[warp] = d1 + g_att[2 * DIM];
        g_s2[warp] = d2 + g_att[2 * DIM + 1];
    }
}

// ---------------- K2: fill buckets; 2 edges/thread (PDL after scores) ------------
__global__ void k_fill(const int* __restrict__ idx, int E) {
    int e2 = (blockIdx.x * blockDim.x + threadIdx.x) * 2;
    if (e2 >= E) {
        cudaGridDependencySynchronize();
        return;
    }
    // independent prologue: edge index loads
    int2 ss = *(const int2*)(idx + e2);
    int2 dd = *(const int2*)(idx + E + e2);

    cudaGridDependencySynchronize();  // wait for s1/s2

    {
        float w = __expf(lrelu(g_s1[ss.x] + g_s2[dd.x]));
        unsigned hw = (unsigned)__half_as_ushort(__float2half_rn(w));
        int pos = atomicAdd(&g_counts[dd.x], 1);
        pos = min(pos, SLOTS - 1);
        g_bucket[(size_t)dd.x * SLOTS + pos] = (hw << 16) | (unsigned)ss.x;
    }
    if (e2 + 1 < E) {
        float w = __expf(lrelu(g_s1[ss.y] + g_s2[dd.y]));
        unsigned hw = (unsigned)__half_as_ushort(__float2half_rn(w));
        int pos = atomicAdd(&g_counts[dd.y], 1);
        pos = min(pos, SLOTS - 1);
        g_bucket[(size_t)dd.y * SLOTS + pos] = (hw << 16) | (unsigned)ss.y;
    }
}

// ---------------- K3 (PROFILED): aggregation (PDL after fill) --------------------
__global__ void __launch_bounds__(256) k_aggregate(int N) {
    cudaGridDependencySynchronize();  // wait for buckets/counts

    int d = (blockIdx.x * blockDim.x + threadIdx.x) >> 5;
    int lane = threadIdx.x & 31;
    if (d >= N) return;
    int cnt = min(g_counts[d], SLOTS);
    const unsigned* B = g_bucket + (size_t)d * SLOTS;
    const uint4* B4 = (const uint4*)B;
    int g = lane >> 4, l16 = lane & 15;
    const char* featB = (const char*)g_featH + l16 * 16;

    float wsum = 0.f;
    for (int j = lane; j < cnt; j += 32)
        wsum += __half2float(__ushort_as_half((unsigned short)(B[j] >> 16)));
    #pragma unroll
    for (int o = 16; o > 0; o >>= 1)
        wsum += __shfl_xor_sync(0xffffffffu, wsum, o);

    __half2 acc[4];
    #pragma unroll
    for (int q = 0; q < 4; q++) acc[q] = __float2half2_rn(0.f);

    int j = 0;
    for (; j + 8 <= cnt; j += 8) {
        uint4 qe = B4[(j >> 2) + g];
        uint4 r0 = *(const uint4*)(featB + ((size_t)(qe.x & 0xFFFFu) << 8));
        uint4 r1 = *(const uint4*)(featB + ((size_t)(qe.y & 0xFFFFu) << 8));
        uint4 r2 = *(const uint4*)(featB + ((size_t)(qe.z & 0xFFFFu) << 8));
        uint4 r3 = *(const uint4*)(featB + ((size_t)(qe.w & 0xFFFFu) << 8));
        unsigned w0u = __byte_perm(qe.x, qe.x, 0x3232);
        unsigned w1u = __byte_perm(qe.y, qe.y, 0x3232);
        unsigned w2u = __byte_perm(qe.z, qe.z, 0x3232);
        unsigned w3u = __byte_perm(qe.w, qe.w, 0x3232);
        __half2 w0 = *(__half2*)&w0u, w1 = *(__half2*)&w1u;
        __half2 w2 = *(__half2*)&w2u, w3 = *(__half2*)&w3u;
        acc[0] = __hfma2(w0, *(__half2*)&r0.x, acc[0]);
        acc[1] = __hfma2(w0, *(__half2*)&r0.y, acc[1]);
        acc[2] = __hfma2(w0, *(__half2*)&r0.z, acc[2]);
        acc[3] = __hfma2(w0, *(__half2*)&r0.w, acc[3]);
        acc[0] = __hfma2(w1, *(__half2*)&r1.x, acc[0]);
        acc[1] = __hfma2(w1, *(__half2*)&r1.y, acc[1]);
        acc[2] = __hfma2(w1, *(__half2*)&r1.z, acc[2]);
        acc[3] = __hfma2(w1, *(__half2*)&r1.w, acc[3]);
        acc[0] = __hfma2(w2, *(__half2*)&r2.x, acc[0]);
        acc[1] = __hfma2(w2, *(__half2*)&r2.y, acc[1]);
        acc[2] = __hfma2(w2, *(__half2*)&r2.z, acc[2]);
        acc[3] = __hfma2(w2, *(__half2*)&r2.w, acc[3]);
        acc[0] = __hfma2(w3, *(__half2*)&r3.x, acc[0]);
        acc[1] = __hfma2(w3, *(__half2*)&r3.y, acc[1]);
        acc[2] = __hfma2(w3, *(__half2*)&r3.z, acc[2]);
        acc[3] = __hfma2(w3, *(__half2*)&r3.w, acc[3]);
    }
    for (; j + 2 <= cnt; j += 2) {
        unsigned e = B[j + g];
        uint4 r = *(const uint4*)(featB + ((size_t)(e & 0xFFFFu) << 8));
        unsigned wu = __byte_perm(e, e, 0x3232);
        __half2 w = *(__half2*)&wu;
        acc[0] = __hfma2(w, *(__half2*)&r.x, acc[0]);
        acc[1] = __hfma2(w, *(__half2*)&r.y, acc[1]);
        acc[2] = __hfma2(w, *(__half2*)&r.z, acc[2]);
        acc[3] = __hfma2(w, *(__half2*)&r.w, acc[3]);
    }
    if (j < cnt && g == 0) {
        unsigned e = B[j];
        uint4 r = *(const uint4*)(featB + ((size_t)(e & 0xFFFFu) << 8));
        unsigned wu = __byte_perm(e, e, 0x3232);
        __half2 w = *(__half2*)&wu;
        acc[0] = __hfma2(w, *(__half2*)&r.x, acc[0]);
        acc[1] = __hfma2(w, *(__half2*)&r.y, acc[1]);
        acc[2] = __hfma2(w, *(__half2*)&r.z, acc[2]);
        acc[3] = __hfma2(w, *(__half2*)&r.w, acc[3]);
    }

    #pragma unroll
    for (int q = 0; q < 4; q++) {
        unsigned v = *(unsigned*)&acc[q];
        unsigned o = __shfl_xor_sync(0xffffffffu, v, 16);
        acc[q] = __hadd2(acc[q], *(__half2*)&o);
    }

    if (lane == 0) g_counts[d] = 0;

    if (g == 0) {
        float inv = 1.f / (wsum + 1e-9f);
        uint4 pk;
        unsigned* pku = (unsigned*)&pk;
        #pragma unroll
        for (int q = 0; q < 4; q++) {
            float2 aq = __half22float2(acc[q]);
            __half2 p = __floats2half2_rn(aq.x * inv, aq.y * inv);
            pku[q] = *(unsigned*)&p;
        }
        *(uint4*)(g_aggH + (size_t)d * DIM + l16 * 8) = pk;
    }
}

// ---------------- K4: fused double HMMA GEMM (PDL after agg) ---------------------
static constexpr int SM_B1 = 0;
static constexpr int SM_B2 = 512;
static constexpr int SM_A  = 1024;                 // 128*PAD halfs = 34816B
static constexpr int SM_W1 = SM_A + 128 * PAD * 2;
static constexpr int SM_W2 = SM_W1 + 128 * PAD * 2;
static constexpr int SMEMF = SM_W2 + 128 * PAD * 2;  // 105472B

__global__ void __launch_bounds__(512, 1)
k_gemm(const float* __restrict__ feat,
       const float* __restrict__ b1, const float* __restrict__ b2,
       float* __restrict__ out, int N) {
    extern __shared__ char sm[];
    uint32_t smb;
    asm("{ .reg .u64 t; cvta.to.shared.u64 t, %1; cvt.u32.u64 %0, t; }" : "=r"(smb) : "l"(sm));
    int tid = threadIdx.x, wid = tid >> 5, lane = tid & 31;
    int row0 = blockIdx.x * 128;

    int m0 = (wid >> 2) * 32, n0 = (wid & 3) * 32;
    int g = lane >> 2, t4 = lane & 3;

    // ---- independent prologue (overlaps agg via PDL): feat prefetch +
    //      weight/bias staging — none of this depends on g_aggH ----
    float2 fC[2][2][4];  // [mi][lo/hi][ni]
    #pragma unroll
    for (int mi = 0; mi < 2; mi++) {
        int rlo = m0 + mi * 16 + g, rhi = rlo + 8;
        int glo = row0 + rlo, ghi = row0 + rhi;
        #pragma unroll
        for (int ni = 0; ni < 4; ni++) {
            int col = n0 + ni * 8 + t4 * 2;
            fC[mi][0][ni] = make_float2(0.f, 0.f);
            fC[mi][1][ni] = make_float2(0.f, 0.f);
            if (glo < N) fC[mi][0][ni] = *(const float2*)(feat + (size_t)glo * DIM + col);
            if (ghi < N) fC[mi][1][ni] = *(const float2*)(feat + (size_t)ghi * DIM + col);
        }
    }
    {
        const uint4* w1 = (const uint4*)g_W1T;
        const uint4* w2 = (const uint4*)g_W2T;
        uint4* s1p = (uint4*)(sm + SM_W1);
        uint4* s2p = (uint4*)(sm + SM_W2);
        #pragma unroll 4
        for (int i = tid; i < 128 * PAD / 8; i += 512) { s1p[i] = w1[i]; s2p[i] = w2[i]; }
        if (tid < 128) {
            ((float*)(sm + SM_B1))[tid] = b1[tid];
            ((float*)(sm + SM_B2))[tid] = b2[tid];
        }
    }

    cudaGridDependencySynchronize();  // wait for g_aggH

    {
        #pragma unroll
        for (int i = tid; i < 128 * 16; i += 512) {
            int r = i >> 4, c8 = (i & 15) << 3;
            int gr = row0 + r;
            uint4 v = make_uint4(0u, 0u, 0u, 0u);
            if (gr < N) v = *(const uint4*)(g_aggH + (size_t)gr * DIM + c8);
            *(uint4*)(sm + SM_A + (r * PAD + c8) * 2) = v;
        }
    }
    __syncthreads();

    uint32_t aAddrBase = smb + SM_A + ((m0 + (lane & 15)) * PAD + (lane >> 4) * 8) * 2;

    // ---- GEMM1 ----
    float c[2][4][4];
    #pragma unroll
    for (int mi = 0; mi < 2; mi++)
        #pragma unroll
        for (int ni = 0; ni < 4; ni++)
            #pragma unroll
            for (int q = 0; q < 4; q++) c[mi][ni][q] = 0.f;

    #pragma unroll
    for (int kc = 0; kc < 8; kc++) {
        uint32_t a[2][4];
        ldmatrix4(a[0], aAddrBase + kc * 32);
        ldmatrix4(a[1], aAddrBase + 16 * PAD * 2 + kc * 32);
        #pragma unroll
        for (int ni = 0; ni < 4; ni++) {
            const char* bp = sm + SM_W1 + ((n0 + ni * 8 + g) * PAD + kc * 16 + t4 * 2) * 2;
            uint32_t b0 = *(const uint32_t*)bp;
            uint32_t b1r = *(const uint32_t*)(bp + 16);
            mma16816(c[0][ni], a[0], b0, b1r);
            mma16816(c[1][ni], a[1], b0, b1r);
        }
    }

    float hn[2][4][4];
    #pragma unroll
    for (int ni = 0; ni < 4; ni++) {
        int col = n0 + ni * 8 + t4 * 2;
        float bb0 = ((const float*)(sm + SM_B1))[col];
        float bb1 = ((const float*)(sm + SM_B1))[col + 1];
        #pragma unroll
        for (int mi = 0; mi < 2; mi++) {
            hn[mi][ni][0] = c[mi][ni][0] + bb0;
            hn[mi][ni][1] = c[mi][ni][1] + bb1;
            hn[mi][ni][2] = c[mi][ni][2] + bb0;
            hn[mi][ni][3] = c[mi][ni][3] + bb1;
        }
    }
    __syncthreads();

    // ---- prod tile (cached feat) ----
    #pragma unroll
    for (int mi = 0; mi < 2; mi++) {
        int rlo = m0 + mi * 16 + g, rhi = rlo + 8;
        #pragma unroll
        for (int ni = 0; ni < 4; ni++) {
            int col = n0 + ni * 8 + t4 * 2;
            float2 flo = fC[mi][0][ni], fhi = fC[mi][1][ni];
            __half2 plo = __floats2half2_rn(flo.x * hn[mi][ni][0], flo.y * hn[mi][ni][1]);
            __half2 phi = __floats2half2_rn(fhi.x * hn[mi][ni][2], fhi.y * hn[mi][ni][3]);
            *(__half2*)(sm + SM_A + (rlo * PAD + col) * 2) = plo;
            *(__half2*)(sm + SM_A + (rhi * PAD + col) * 2) = phi;
        }
    }
    __syncthreads();

    // ---- GEMM2 ----
    #pragma unroll
    for (int mi = 0; mi < 2; mi++)
        #pragma unroll
        for (int ni = 0; ni < 4; ni++)
            #pragma unroll
            for (int q = 0; q < 4; q++) c[mi][ni][q] = 0.f;

    #pragma unroll
    for (int kc = 0; kc < 8; kc++) {
        uint32_t a[2][4];
        ldmatrix4(a[0], aAddrBase + kc * 32);
        ldmatrix4(a[1], aAddrBase + 16 * PAD * 2 + kc * 32);
        #pragma unroll
        for (int ni = 0; ni < 4; ni++) {
            const char* bp = sm + SM_W2 + ((n0 + ni * 8 + g) * PAD + kc * 16 + t4 * 2) * 2;
            uint32_t b0 = *(const uint32_t*)bp;
            uint32_t b1r = *(const uint32_t*)(bp + 16);
            mma16816(c[0][ni], a[0], b0, b1r);
            mma16816(c[1][ni], a[1], b0, b1r);
        }
    }

    // ---- epilogue (cached feat) ----
    #pragma unroll
    for (int mi = 0; mi < 2; mi++) {
        int rlo = m0 + mi * 16 + g, rhi = rlo + 8;
        int glo = row0 + rlo, ghi = row0 + rhi;
        #pragma unroll
        for (int ni = 0; ni < 4; ni++) {
            int col = n0 + ni * 8 + t4 * 2;
            float bb0 = ((const float*)(sm + SM_B2))[col];
            float bb1 = ((const float*)(sm + SM_B2))[col + 1];
            if (glo < N) {
                float2 f = fC[mi][0][ni];
                float2 o;
                o.x = lrelu(c[mi][ni][0] + bb0 + f.x + hn[mi][ni][0]);
                o.y = lrelu(c[mi][ni][1] + bb1 + f.y + hn[mi][ni][1]);
                *(float2*)(out + (size_t)glo * DIM + col) = o;
            }
            if (ghi < N) {
                float2 f = fC[mi][1][ni];
                float2 o;
                o.x = lrelu(c[mi][ni][2] + bb0 + f.x + hn[mi][ni][2]);
                o.y = lrelu(c[mi][ni][3] + bb1 + f.y + hn[mi][ni][3]);
                *(float2*)(out + (size_t)ghi * DIM + col) = o;
            }
        }
    }
}

// ---------------- launch ----------------
template <typename... Args>
static void launch_pdl(void (*kern)(Args...), dim3 grid, dim3 block, size_t smem,
                       Args... args) {
    cudaLaunchConfig_t cfg = {};
    cfg.gridDim = grid;
    cfg.blockDim = block;
    cfg.dynamicSmemBytes = smem;
    cfg.stream = 0;
    cudaLaunchAttribute attr[1];
    attr[0].id = cudaLaunchAttributeProgrammaticStreamSerialization;
    attr[0].val.programmaticStreamSerializationAllowed = 1;
    cfg.attrs = attr;
    cfg.numAttrs = 1;
    cudaLaunchKernelEx(&cfg, kern, args...);
}

extern "C" void kernel_launch(void* const* d_in, const int* in_sizes, int n_in,
                              void* d_out, int out_size) {
    const int*   indices  = (const int*)d_in[0];
    const float* features = (const float*)d_in[1];
    const float* W1_w   = (const float*)d_in[3];
    const float* W1_b   = (const float*)d_in[4];
    const float* W2_w   = (const float*)d_in[5];
    const float* W2_b   = (const float*)d_in[6];
    const float* Watt_w = (const float*)d_in[7];
    const float* Watt_b = (const float*)d_in[8];
    const float* a_vec  = (const float*)d_in[9];

    int E = in_sizes[0] / 2;
    int N = in_sizes[1] / DIM;

    cudaFuncSetAttribute((const void*)k_gemm,
                         cudaFuncAttributeMaxDynamicSharedMemorySize, SMEMF);

    float* out = (float*)d_out;

    // slot 1 (plain)
    k_attw<<<17, 256>>>(Watt_w, Watt_b, a_vec, W1_w, W2_w);
    // slot 2 (PDL after attw)
    launch_pdl(k_node_scores, dim3((N * 32 + 255) / 256), dim3(256), 0, features, N);
    // slot 3 (PDL after scores)
    launch_pdl(k_fill, dim3(((E + 1) / 2 + 255) / 256), dim3(256), 0, indices, E);
    // slot 4 (profiled; PDL after fill)
    launch_pdl(k_aggregate, dim3((N * 32 + 255) / 256), dim3(256), 0, N);
    // slot 5 (PDL after agg — prologue overlaps aggregation tail)
    launch_pdl(k_gemm, dim3((N + 127) / 128), dim3(512), (size_t)SMEMF,
               features, W1_b, W2_b, out, N);
}